// round 5
// baseline (speedup 1.0000x reference)
#include <cuda_runtime.h>
#include <cuda_bf16.h>

// PostProcessor3D: threshold(0.9) -> 5x5x5 maxpool(stride1,pad2) -> strict peak mask.
// In: [64,512,512] f32.  Out: [64,512,512] f32.
//
// Block (128,4)=512 threads covers full W=512 (float4/thread) x 4 H rows,
// marching 36 planes of a 32-deep D chunk. Grid 128x2 = 256 blocks, ALL
// co-resident (2 blocks/SM on most SMs -> barrier overlap, 148 SMs busy).
//
// Separable order: H-max first (smem, 5 coalesced float4 LDS), then W-max in
// registers via warp shuffles; warp-edge columns via predicated float2 LDS on
// lanes 0/31. ONE barrier per plane (double-buffered smem).
// -inf pad == 0 pad since thresholded values >= 0.
//
// D-dimension peak identity (2-deep candidate ring):
//   s(p)  = (cen(p)==m2d(p)) ? cen(p) : 0
//   cn(p) = (s >= m2d(p-1) && s >= m2d(p-2)) ? s : 0
//   out(q)= (cn(q) >= m2d(q+1) && cn(q) >= m2d(q+2)) ? cn(q) : 0, emitted p=q+2.

#define Wd 512
#define Hd 512
#define Dd 64
#define TH 4            // output rows per block
#define LR 8            // loaded rows (TH + 4)
#define DCH 32          // output planes per block
#define NP (DCH + 4)    // planes iterated
#define PSZ (Hd * Wd)   // plane size
#define THRESH 0.9f

__device__ __forceinline__ float thr(float x) { return x > THRESH ? x : 0.f; }
__device__ __forceinline__ float4 thr4(float4 a) {
    return make_float4(thr(a.x), thr(a.y), thr(a.z), thr(a.w));
}
__device__ __forceinline__ float4 fmax4(float4 a, float4 b) {
    return make_float4(fmaxf(a.x, b.x), fmaxf(a.y, b.y),
                       fmaxf(a.z, b.z), fmaxf(a.w, b.w));
}

__global__ __launch_bounds__(512, 2)
void peak3d_kernel(const float* __restrict__ in, float* __restrict__ out) {
    __shared__ float vsm[2][LR][512];      // thresholded planes, double-buffered

    const int tx   = threadIdx.x;          // 0..127
    const int ty   = threadIdx.y;          // 0..3
    const int lane = tx & 31;
    const int c    = tx << 2;              // column base (float4)
    const int h0   = blockIdx.x * TH;
    const int d0   = blockIdx.y * DCH;

    // warp-edge extension columns (hmax at c-2..c-1 for lane0, c+4..c+5 for lane31)
    const bool edgeL    = (lane == 0);
    const bool edgeR    = (lane == 31);
    const bool haveEdge = (edgeL && tx != 0) || (edgeR && tx != 127);
    const int  ec       = edgeL ? (c - 2) : (c + 4);

    // this thread loads rows ty and ty+4 of the 8-row strip [h0-2, h0+5]
    const int  k2  = ty + 4;
    const int  gh1 = h0 - 2 + ty;
    const int  gh2 = h0 + 2 + ty;
    const bool ok1 = ((unsigned)gh1 < (unsigned)Hd);
    const bool ok2 = (gh2 < Hd);

    // incremental global pointers (advance by PSZ per plane)
    const float* g1 = in + (size_t)gh1 * Wd + c;   // + dl*PSZ added via bump
    const float* g2 = in + (size_t)gh2 * Wd + c;

    // ---- prologue: fetch plane p=0 (dl = d0-2), store thresholded to buffer 0 ----
    float4 a1 = make_float4(0.f, 0.f, 0.f, 0.f), a2 = a1;
    {
        int dl = d0 - 2;
        if (dl >= 0) {
            if (ok1) a1 = *(const float4*)(g1 + (size_t)dl * PSZ);
            if (ok2) a2 = *(const float4*)(g2 + (size_t)dl * PSZ);
        }
    }
    *(float4*)(&vsm[0][ty][c]) = thr4(a1);
    *(float4*)(&vsm[0][k2][c]) = thr4(a2);

    // pointers positioned at plane dl = d0-1 (first prefetch target)
    const float* p1 = g1 + (size_t)(d0 - 1 < 0 ? 0 : d0 - 1) * PSZ;
    const float* p2 = g2 + (size_t)(d0 - 1 < 0 ? 0 : d0 - 1) * PSZ;

    // ring state
    float4 rp1  = make_float4(0.f, 0.f, 0.f, 0.f);   // m2d(p-1)
    float4 rp2  = rp1;                               // m2d(p-2)
    float4 cnd0 = rp1, cnd1 = rp1;                   // cn ring (2 deep)

    float* outp = out + (size_t)d0 * PSZ + (size_t)(h0 + ty) * Wd + c;

    for (int p = 0; p < NP; ++p) {
        const int b = p & 1;
        const float* vb = &vsm[b][0][0];

        __syncthreads();   // vsm[b] stores done; prior reads of vsm[b^1] done

        // ---- prefetch plane p+1 into registers (hidden under compute) ----
        a1 = make_float4(0.f, 0.f, 0.f, 0.f); a2 = a1;
        {
            int dln = d0 - 1 + p;           // = d0-2 + (p+1)
            if (dln >= 0 && dln < Dd && (p + 1) < NP) {
                if (ok1) a1 = *(const float4*)(p1);
                if (ok2) a2 = *(const float4*)(p2);
            }
            if (dln >= 0) { p1 += PSZ; p2 += PSZ; }
        }

        // ---- H-max (window 5) over loaded rows ty..ty+4 at cols c..c+3 ----
        const float* vr = vb + ty * 512 + c;
        float4 t0 = *(const float4*)(vr);
        float4 t1 = *(const float4*)(vr + 512);
        float4 t2 = *(const float4*)(vr + 1024);   // center row -> cen
        float4 t3 = *(const float4*)(vr + 1536);
        float4 t4 = *(const float4*)(vr + 2048);
        float4 cen = t2;
        float4 hm  = fmax4(fmax4(fmax4(t0, t1), fmax4(t2, t3)), t4);

        // edge lanes also compute H-max for the 2 extension columns
        float2 eh = make_float2(0.f, 0.f);
        if (haveEdge) {
            const float* ep = vb + ty * 512 + ec;
            float2 e0 = *(const float2*)(ep);
            float2 e1 = *(const float2*)(ep + 512);
            float2 e2 = *(const float2*)(ep + 1024);
            float2 e3 = *(const float2*)(ep + 1536);
            float2 e4 = *(const float2*)(ep + 2048);
            eh.x = fmaxf(fmaxf(fmaxf(e0.x, e1.x), fmaxf(e2.x, e3.x)), e4.x);
            eh.y = fmaxf(fmaxf(fmaxf(e0.y, e1.y), fmaxf(e2.y, e3.y)), e4.y);
        }

        // ---- W-max (window 5) in registers via shuffles ----
        float l2 = __shfl_up_sync(0xffffffffu, hm.z, 1);
        float l1 = __shfl_up_sync(0xffffffffu, hm.w, 1);
        float r4 = __shfl_down_sync(0xffffffffu, hm.x, 1);
        float r5 = __shfl_down_sync(0xffffffffu, hm.y, 1);
        if (edgeL) { l2 = eh.x; l1 = eh.y; }   // eh==0 at global W edge
        if (edgeR) { r4 = eh.x; r5 = eh.y; }

        float m01 = fmaxf(hm.x, hm.y);
        float m12 = fmaxf(hm.y, hm.z);
        float m23 = fmaxf(hm.z, hm.w);
        float4 m;  // m2d(p) for cols c..c+3
        m.x = fmaxf(fmaxf(l2, l1), fmaxf(m01, hm.z));
        m.y = fmaxf(l1, fmaxf(m01, m23));
        m.z = fmaxf(fmaxf(m01, m23), r4);
        m.w = fmaxf(fmaxf(m12, hm.w), fmaxf(r4, r5));

        // ---- D rings + emit ----
        float4 s;
        s.x = (cen.x == m.x) ? cen.x : 0.f;
        s.y = (cen.y == m.y) ? cen.y : 0.f;
        s.z = (cen.z == m.z) ? cen.z : 0.f;
        s.w = (cen.w == m.w) ? cen.w : 0.f;

        float4 cn;
        cn.x = (s.x >= rp1.x && s.x >= rp2.x) ? s.x : 0.f;
        cn.y = (s.y >= rp1.y && s.y >= rp2.y) ? s.y : 0.f;
        cn.z = (s.z >= rp1.z && s.z >= rp2.z) ? s.z : 0.f;
        cn.w = (s.w >= rp1.w && s.w >= rp2.w) ? s.w : 0.f;

        if (p >= 4) {
            // cnd0 = cn(p-2); gates m2d(p-1)=rp1, m2d(p)=m
            float4 o;
            o.x = (cnd0.x >= rp1.x && cnd0.x >= m.x) ? cnd0.x : 0.f;
            o.y = (cnd0.y >= rp1.y && cnd0.y >= m.y) ? cnd0.y : 0.f;
            o.z = (cnd0.z >= rp1.z && cnd0.z >= m.z) ? cnd0.z : 0.f;
            o.w = (cnd0.w >= rp1.w && cnd0.w >= m.w) ? cnd0.w : 0.f;
            *(float4*)outp = o;
            outp += PSZ;
        }

        cnd0 = cnd1; cnd1 = cn;
        rp2  = rp1;  rp1  = m;

        // ---- store prefetched plane (thresholded) into the other buffer ----
        *(float4*)(&vsm[b ^ 1][ty][c]) = thr4(a1);
        *(float4*)(&vsm[b ^ 1][k2][c]) = thr4(a2);
    }
}

extern "C" void kernel_launch(void* const* d_in, const int* in_sizes, int n_in,
                              void* d_out, int out_size) {
    (void)in_sizes; (void)n_in; (void)out_size;
    const float* in = (const float*)d_in[0];
    float* out = (float*)d_out;

    dim3 block(128, 4);                 // 512 threads
    dim3 grid(Hd / TH, Dd / DCH);       // 128 x 2 = 256 blocks (all resident)
    peak3d_kernel<<<grid, block>>>(in, out);
}

// round 6
// speedup vs baseline: 2.0100x; 2.0100x over previous
#include <cuda_runtime.h>
#include <cuda_bf16.h>
#include <cstdint>

// PostProcessor3D: threshold(0.9) -> 5x5x5 maxpool(stride1,pad2) -> strict peak mask.
// In: [64,512,512] f32.  Out: [64,512,512] f32.
//
// Block (128,8)=1024 threads, full W=512 (float4/thread) x 8 H rows, marching
// 36 planes of a 32-deep D chunk. Grid 64x2 = 128 blocks.
//
// All max work in RAW domain (thr commutes with max; pads are 0 and thr(0)=0).
// Threshold applied once at emission:
//   out(od) = (cen==M3d && cen>THRESH) ? cen : 0,  M3d = max(m2d ring of 5).
//
// cp.async prefetch into a 3-buffer smem ring (lookahead 1, one barrier/plane):
//   iter p: issue plane p+1 -> buf (p+1)%3 ; commit ; wait_group 1 ; BAR ; read buf p%3.
// Safety: writes at iter p hit buf (p-2)%3, whose readers finished before barrier p-1.

#define Wd 512
#define Hd 512
#define Dd 64
#define TH 8
#define LR 12
#define DCH 32
#define NP (DCH + 4)        // 36
#define PSZ (Hd * Wd)
#define THRESH 0.9f
#define BUFSZ (LR * Wd)     // floats per buffer

__device__ __forceinline__ void cp_async16(uint32_t dst, const void* src, int src_bytes) {
    asm volatile("cp.async.cg.shared.global [%0], [%1], 16, %2;\n"
                 :: "r"(dst), "l"(src), "r"(src_bytes));
}
__device__ __forceinline__ void cp_commit() {
    asm volatile("cp.async.commit_group;\n");
}
__device__ __forceinline__ void cp_wait1() {
    asm volatile("cp.async.wait_group 1;\n");
}
__device__ __forceinline__ void cp_wait0() {
    asm volatile("cp.async.wait_group 0;\n");
}

__device__ __forceinline__ float4 fmax4(float4 a, float4 b) {
    return make_float4(fmaxf(a.x, b.x), fmaxf(a.y, b.y),
                       fmaxf(a.z, b.z), fmaxf(a.w, b.w));
}

extern __shared__ float vsm[];   // [3][LR][512] raw planes

__global__ __launch_bounds__(1024, 1)
void peak3d_kernel(const float* __restrict__ in, float* __restrict__ out) {
    const int tx   = threadIdx.x;          // 0..127
    const int ty   = threadIdx.y;          // 0..7
    const int lane = tx & 31;
    const int c    = tx << 2;
    const int h0   = blockIdx.x * TH;
    const int d0   = blockIdx.y * DCH;

    // warp-edge extension cols (W-max needs c-2..c-1 / c+4..c+5 on lanes 0/31)
    const bool edgeL    = (lane == 0);
    const bool edgeR    = (lane == 31);
    const bool haveEdge = (edgeL && tx != 0) || (edgeR && tx != 127);
    const int  ec       = edgeL ? (c - 2) : (c + 4);

    // this thread copies loaded-row ty, and (ty<4) loaded-row 8+ty
    const int  k2   = 8 + ty;
    const bool has2 = (ty < 4);
    const int  gh1  = h0 - 2 + ty;
    const int  gh2  = h0 + 6 + ty;
    const bool ok1  = ((unsigned)gh1 < (unsigned)Hd);
    const bool ok2  = has2 && (gh2 < Hd);

    const float* g1 = in + (size_t)(ok1 ? gh1 : 0) * Wd + c;
    const float* g2 = in + (size_t)(ok2 ? gh2 : 0) * Wd + c;

    const uint32_t sbase = (uint32_t)__cvta_generic_to_shared(vsm);
    const uint32_t dst1  = sbase + (uint32_t)(ty * Wd + c) * 4u;
    const uint32_t dst2  = sbase + (uint32_t)(k2 * Wd + c) * 4u;
    const uint32_t BUFB  = BUFSZ * 4u;     // bytes per buffer

    // issue async copies for plane index pf (dl = d0-2+pf) into buf pf%3
    auto issue = [&](int pf) {
        int  dl  = d0 - 2 + pf;
        bool dok = ((unsigned)dl < (unsigned)Dd) && (pf < NP);
        int  dlc = ((unsigned)dl < (unsigned)Dd) ? dl : 0;
        uint32_t boff = (uint32_t)(pf % 3) * BUFB;
        const float* s1 = g1 + (size_t)dlc * PSZ;
        cp_async16(dst1 + boff, s1, (ok1 && dok) ? 16 : 0);
        if (has2) {
            const float* s2 = g2 + (size_t)dlc * PSZ;
            cp_async16(dst2 + boff, s2, (ok2 && dok) ? 16 : 0);
        }
        cp_commit();
    };

    issue(0);   // plane 0 -> buf 0

    // rings (raw domain)
    float4 rp1 = make_float4(0.f, 0.f, 0.f, 0.f);
    float4 rp2 = rp1, rp3 = rp1, rp4 = rp1;          // m2d(p-1..p-4)
    float4 cen1 = rp1, cen2 = rp1;                   // cen(p-1), cen(p-2)

    float* outp = out + (size_t)d0 * PSZ + (size_t)(h0 + ty) * Wd + c;

    #pragma unroll 3
    for (int p = 0; p < NP; ++p) {
        issue(p + 1);
        cp_wait1();         // plane p's copies (this thread) complete
        __syncthreads();    // all threads' plane-p copies visible

        const float* vb = vsm + (p % 3) * BUFSZ;

        // ---- H-max (window 5) over rows ty..ty+4, cols c..c+3 (raw) ----
        const float* vr = vb + ty * Wd + c;
        float4 t0 = *(const float4*)(vr);
        float4 t1 = *(const float4*)(vr + 512);
        float4 t2 = *(const float4*)(vr + 1024);   // center row
        float4 t3 = *(const float4*)(vr + 1536);
        float4 t4 = *(const float4*)(vr + 2048);
        float4 cen = t2;
        float4 hm  = fmax4(fmax4(fmax4(t0, t1), fmax4(t2, t3)), t4);

        float2 eh = make_float2(0.f, 0.f);
        if (haveEdge) {
            const float* ep = vb + ty * Wd + ec;
            float2 e0 = *(const float2*)(ep);
            float2 e1 = *(const float2*)(ep + 512);
            float2 e2 = *(const float2*)(ep + 1024);
            float2 e3 = *(const float2*)(ep + 1536);
            float2 e4 = *(const float2*)(ep + 2048);
            eh.x = fmaxf(fmaxf(fmaxf(e0.x, e1.x), fmaxf(e2.x, e3.x)), e4.x);
            eh.y = fmaxf(fmaxf(fmaxf(e0.y, e1.y), fmaxf(e2.y, e3.y)), e4.y);
        }

        // ---- W-max (window 5) via shuffles ----
        float l2 = __shfl_up_sync(0xffffffffu, hm.z, 1);
        float l1 = __shfl_up_sync(0xffffffffu, hm.w, 1);
        float r4 = __shfl_down_sync(0xffffffffu, hm.x, 1);
        float r5 = __shfl_down_sync(0xffffffffu, hm.y, 1);
        if (edgeL) { l2 = eh.x; l1 = eh.y; }   // 0 at global W edge (raw pad 0 ok)
        if (edgeR) { r4 = eh.x; r5 = eh.y; }

        float m01 = fmaxf(hm.x, hm.y);
        float m12 = fmaxf(hm.y, hm.z);
        float m23 = fmaxf(hm.z, hm.w);
        float4 m;                               // m2d(p), raw
        m.x = fmaxf(fmaxf(l2, l1), fmaxf(m01, hm.z));
        m.y = fmaxf(l1, fmaxf(m01, m23));
        m.z = fmaxf(fmaxf(m01, m23), r4);
        m.w = fmaxf(fmaxf(m12, hm.w), fmaxf(r4, r5));

        // ---- emit plane od = d0 + (p-4): window = m2d(p-4..p), center = cen(p-2) ----
        if (p >= 4) {
            float4 M3 = fmax4(fmax4(fmax4(rp4, rp3), fmax4(rp2, rp1)), m);
            float4 o;
            o.x = (cen2.x == M3.x && cen2.x > THRESH) ? cen2.x : 0.f;
            o.y = (cen2.y == M3.y && cen2.y > THRESH) ? cen2.y : 0.f;
            o.z = (cen2.z == M3.z && cen2.z > THRESH) ? cen2.z : 0.f;
            o.w = (cen2.w == M3.w && cen2.w > THRESH) ? cen2.w : 0.f;
            *(float4*)outp = o;
            outp += PSZ;
        }

        rp4 = rp3; rp3 = rp2; rp2 = rp1; rp1 = m;
        cen2 = cen1; cen1 = cen;
    }

    cp_wait0();   // drain last (unread) prefetch group before exit
}

extern "C" void kernel_launch(void* const* d_in, const int* in_sizes, int n_in,
                              void* d_out, int out_size) {
    (void)in_sizes; (void)n_in; (void)out_size;
    const float* in = (const float*)d_in[0];
    float* out = (float*)d_out;

    const int smem_bytes = 3 * BUFSZ * (int)sizeof(float);   // 73728
    cudaFuncSetAttribute(peak3d_kernel,
                         cudaFuncAttributeMaxDynamicSharedMemorySize, smem_bytes);

    dim3 block(128, 8);                 // 1024 threads
    dim3 grid(Hd / TH, Dd / DCH);       // 64 x 2 = 128 blocks
    peak3d_kernel<<<grid, block, smem_bytes>>>(in, out);
}

// round 7
// speedup vs baseline: 2.1708x; 1.0800x over previous
#include <cuda_runtime.h>
#include <cuda_bf16.h>
#include <cstdint>

// PostProcessor3D: threshold(0.9) -> 5x5x5 maxpool(stride1,pad2) -> strict peak mask.
// In: [64,512,512] f32.  Out: [64,512,512] f32.
//
// Block (128,8)=1024 threads, full W=512 (float4/thread) x 8 H rows, marching
// 36 planes of a 32-deep D chunk in PAIRS. Grid 64x2 = 128 blocks.
//
// Raw-domain max (thr commutes with max; pads are 0). Threshold at emission:
//   out(od) = (cen==M3d && cen>THRESH) ? cen : 0.
//
// cp.async into a 6-buffer smem ring, 2 planes per iteration, ONE barrier per
// 2 planes, lookahead 2 planes. Per iter k (planes p=2k, p+1):
//   issue p+2 -> buf (p+2)%6, commit; issue p+3 -> buf (p+3)%6, commit;
//   wait_group 2 (p, p+1 complete); BAR; compute p then p+1.
// Race-freedom: writes at iter k+1 hit bufs (p+4)%6,(p+5)%6 whose last readers
// ran in iter k-1, separated by barrier k. Off-range planes commit EMPTY groups
// (no zfill) so they cannot clobber live buffers.

#define Wd 512
#define Hd 512
#define Dd 64
#define TH 8
#define LR 12
#define DCH 32
#define NP (DCH + 4)        // 36 (even)
#define PSZ (Hd * Wd)
#define THRESH 0.9f
#define BUFSZ (LR * Wd)     // floats per buffer
#define NBUF 6

__device__ __forceinline__ void cp_async16(uint32_t dst, const void* src, int src_bytes) {
    asm volatile("cp.async.cg.shared.global [%0], [%1], 16, %2;\n"
                 :: "r"(dst), "l"(src), "r"(src_bytes));
}
__device__ __forceinline__ void cp_commit() {
    asm volatile("cp.async.commit_group;\n");
}
__device__ __forceinline__ void cp_wait2() {
    asm volatile("cp.async.wait_group 2;\n");
}
__device__ __forceinline__ void cp_wait0() {
    asm volatile("cp.async.wait_group 0;\n");
}

__device__ __forceinline__ float4 fmax4(float4 a, float4 b) {
    return make_float4(fmaxf(a.x, b.x), fmaxf(a.y, b.y),
                       fmaxf(a.z, b.z), fmaxf(a.w, b.w));
}

extern __shared__ float vsm[];   // [NBUF][LR][512] raw planes

__global__ __launch_bounds__(1024, 1)
void peak3d_kernel(const float* __restrict__ in, float* __restrict__ out) {
    const int tx   = threadIdx.x;          // 0..127
    const int ty   = threadIdx.y;          // 0..7
    const int lane = tx & 31;
    const int c    = tx << 2;
    const int h0   = blockIdx.x * TH;
    const int d0   = blockIdx.y * DCH;

    const bool edgeL    = (lane == 0);
    const bool edgeR    = (lane == 31);
    const bool haveEdge = (edgeL && tx != 0) || (edgeR && tx != 127);
    const int  ec       = edgeL ? (c - 2) : (c + 4);

    // this thread copies loaded-row ty, and (ty<4) loaded-row 8+ty
    const int  k2   = 8 + ty;
    const bool has2 = (ty < 4);
    const int  gh1  = h0 - 2 + ty;
    const int  gh2  = h0 + 6 + ty;
    const bool ok1  = ((unsigned)gh1 < (unsigned)Hd);
    const bool ok2  = has2 && (gh2 < Hd);

    const float* g1 = in + (size_t)(ok1 ? gh1 : 0) * Wd + c;
    const float* g2 = in + (size_t)(ok2 ? gh2 : 0) * Wd + c;

    const uint32_t sbase = (uint32_t)__cvta_generic_to_shared(vsm);
    const uint32_t dst1  = sbase + (uint32_t)(ty * Wd + c) * 4u;
    const uint32_t dst2  = sbase + (uint32_t)(k2 * Wd + c) * 4u;
    const uint32_t BUFB  = BUFSZ * 4u;

    // issue async copies for plane index pf (dl = d0-2+pf) into buf pf%NBUF.
    // pf >= NP: commit an EMPTY group (keeps wait counts aligned, no writes).
    auto issue = [&](int pf) {
        if (pf < NP) {
            int  dl  = d0 - 2 + pf;
            bool dok = ((unsigned)dl < (unsigned)Dd);
            int  dlc = dok ? dl : 0;
            uint32_t boff = (uint32_t)(pf % NBUF) * BUFB;
            cp_async16(dst1 + boff, g1 + (size_t)dlc * PSZ, (ok1 && dok) ? 16 : 0);
            if (has2)
                cp_async16(dst2 + boff, g2 + (size_t)dlc * PSZ, (ok2 && dok) ? 16 : 0);
        }
        cp_commit();
    };

    issue(0);
    issue(1);

    // rings (raw domain)
    float4 rp1 = make_float4(0.f, 0.f, 0.f, 0.f);
    float4 rp2 = rp1, rp3 = rp1, rp4 = rp1;          // m2d(p-1..p-4)
    float4 cen1 = rp1, cen2 = rp1;                   // cen(p-1), cen(p-2)

    float* outp = out + (size_t)d0 * PSZ + (size_t)(h0 + ty) * Wd + c;

    // compute one plane from buffer vb; returns via ring update + optional emit
    auto plane = [&](const float* vb, bool emit) {
        const float* vr = vb + ty * Wd + c;
        float4 t0 = *(const float4*)(vr);
        float4 t1 = *(const float4*)(vr + 512);
        float4 t2 = *(const float4*)(vr + 1024);   // center row
        float4 t3 = *(const float4*)(vr + 1536);
        float4 t4 = *(const float4*)(vr + 2048);
        float4 cen = t2;
        float4 hm  = fmax4(fmax4(fmax4(t0, t1), fmax4(t2, t3)), t4);

        float2 eh = make_float2(0.f, 0.f);
        if (haveEdge) {
            const float* ep = vb + ty * Wd + ec;
            float2 e0 = *(const float2*)(ep);
            float2 e1 = *(const float2*)(ep + 512);
            float2 e2 = *(const float2*)(ep + 1024);
            float2 e3 = *(const float2*)(ep + 1536);
            float2 e4 = *(const float2*)(ep + 2048);
            eh.x = fmaxf(fmaxf(fmaxf(e0.x, e1.x), fmaxf(e2.x, e3.x)), e4.x);
            eh.y = fmaxf(fmaxf(fmaxf(e0.y, e1.y), fmaxf(e2.y, e3.y)), e4.y);
        }

        float l2 = __shfl_up_sync(0xffffffffu, hm.z, 1);
        float l1 = __shfl_up_sync(0xffffffffu, hm.w, 1);
        float r4 = __shfl_down_sync(0xffffffffu, hm.x, 1);
        float r5 = __shfl_down_sync(0xffffffffu, hm.y, 1);
        if (edgeL) { l2 = eh.x; l1 = eh.y; }
        if (edgeR) { r4 = eh.x; r5 = eh.y; }

        float m01 = fmaxf(hm.x, hm.y);
        float m12 = fmaxf(hm.y, hm.z);
        float m23 = fmaxf(hm.z, hm.w);
        float4 m;                               // m2d(p), raw
        m.x = fmaxf(fmaxf(l2, l1), fmaxf(m01, hm.z));
        m.y = fmaxf(l1, fmaxf(m01, m23));
        m.z = fmaxf(fmaxf(m01, m23), r4);
        m.w = fmaxf(fmaxf(m12, hm.w), fmaxf(r4, r5));

        if (emit) {
            float4 M3 = fmax4(fmax4(fmax4(rp4, rp3), fmax4(rp2, rp1)), m);
            float4 o;
            o.x = (cen2.x == M3.x && cen2.x > THRESH) ? cen2.x : 0.f;
            o.y = (cen2.y == M3.y && cen2.y > THRESH) ? cen2.y : 0.f;
            o.z = (cen2.z == M3.z && cen2.z > THRESH) ? cen2.z : 0.f;
            o.w = (cen2.w == M3.w && cen2.w > THRESH) ? cen2.w : 0.f;
            *(float4*)outp = o;
            outp += PSZ;
        }

        rp4 = rp3; rp3 = rp2; rp2 = rp1; rp1 = m;
        cen2 = cen1; cen1 = cen;
    };

    #pragma unroll 3
    for (int k = 0; k < NP / 2; ++k) {
        const int p = 2 * k;
        issue(p + 2);
        issue(p + 3);
        cp_wait2();         // planes p, p+1 complete (this thread)
        __syncthreads();    // all threads' copies of planes p, p+1 visible

        plane(vsm + (p % NBUF) * BUFSZ,       p     >= 4);
        plane(vsm + ((p + 1) % NBUF) * BUFSZ, p + 1 >= 4);
    }

    cp_wait0();   // drain trailing groups before exit
}

extern "C" void kernel_launch(void* const* d_in, const int* in_sizes, int n_in,
                              void* d_out, int out_size) {
    (void)in_sizes; (void)n_in; (void)out_size;
    const float* in = (const float*)d_in[0];
    float* out = (float*)d_out;

    const int smem_bytes = NBUF * BUFSZ * (int)sizeof(float);   // 147456
    cudaFuncSetAttribute(peak3d_kernel,
                         cudaFuncAttributeMaxDynamicSharedMemorySize, smem_bytes);

    dim3 block(128, 8);                 // 1024 threads
    dim3 grid(Hd / TH, Dd / DCH);       // 64 x 2 = 128 blocks
    peak3d_kernel<<<grid, block, smem_bytes>>>(in, out);
}

// round 8
// speedup vs baseline: 2.3553x; 1.0850x over previous
#include <cuda_runtime.h>
#include <cuda_bf16.h>
#include <cstdint>

// PostProcessor3D: threshold(0.9) -> 5x5x5 maxpool(stride1,pad2) -> strict peak mask.
// In: [64,512,512] f32.  Out: [64,512,512] f32.
//
// Block (128,4)=512 threads, full W=512 (float4/thread) x 4 H rows, marching
// 36 planes of a 32-deep D chunk in PAIRS. Grid 128x2 = 256 blocks, 2 blocks
// co-resident per SM (launch_bounds(512,2), 98KB smem/block) -> barrier and
// latency overlap across blocks, all 148 SMs busy.
//
// Raw-domain max (thr commutes with max; pads are 0). Threshold at emission:
//   out(od) = (cen==M3d && cen>THRESH) ? cen : 0.
//
// cp.async into a 6-buffer smem ring, 2 planes per iteration, ONE barrier per
// 2 planes, lookahead 2 planes. Per iter k (planes p=2k, p+1):
//   issue p+2, p+3 (2 commits); wait_group 2 (p, p+1 done); BAR; compute p, p+1.
// Race-freedom: writes at iter k+1 hit bufs (p+4)%6,(p+5)%6 whose last readers
// ran in iter k-1, separated by barrier k. Off-range planes commit EMPTY groups.

#define Wd 512
#define Hd 512
#define Dd 64
#define TH 4
#define LR 8
#define DCH 32
#define NP (DCH + 4)        // 36 (even)
#define PSZ (Hd * Wd)
#define THRESH 0.9f
#define BUFSZ (LR * Wd)     // floats per buffer (4096)
#define NBUF 6

__device__ __forceinline__ void cp_async16(uint32_t dst, const void* src, int src_bytes) {
    asm volatile("cp.async.cg.shared.global [%0], [%1], 16, %2;\n"
                 :: "r"(dst), "l"(src), "r"(src_bytes));
}
__device__ __forceinline__ void cp_commit() {
    asm volatile("cp.async.commit_group;\n");
}
__device__ __forceinline__ void cp_wait2() {
    asm volatile("cp.async.wait_group 2;\n");
}
__device__ __forceinline__ void cp_wait0() {
    asm volatile("cp.async.wait_group 0;\n");
}

__device__ __forceinline__ float4 fmax4(float4 a, float4 b) {
    return make_float4(fmaxf(a.x, b.x), fmaxf(a.y, b.y),
                       fmaxf(a.z, b.z), fmaxf(a.w, b.w));
}

extern __shared__ float vsm[];   // [NBUF][LR][512] raw planes

__global__ __launch_bounds__(512, 2)
void peak3d_kernel(const float* __restrict__ in, float* __restrict__ out) {
    const int tx   = threadIdx.x;          // 0..127
    const int ty   = threadIdx.y;          // 0..3
    const int lane = tx & 31;
    const int c    = tx << 2;
    const int h0   = blockIdx.x * TH;
    const int d0   = blockIdx.y * DCH;

    const bool edgeL    = (lane == 0);
    const bool edgeR    = (lane == 31);
    const bool haveEdge = (edgeL && tx != 0) || (edgeR && tx != 127);
    const int  ec       = edgeL ? (c - 2) : (c + 4);

    // this thread copies loaded-rows ty and ty+4 of the strip [h0-2, h0+5]
    const int  k2  = ty + 4;
    const int  gh1 = h0 - 2 + ty;
    const int  gh2 = h0 + 2 + ty;
    const bool ok1 = ((unsigned)gh1 < (unsigned)Hd);
    const bool ok2 = (gh2 < Hd);

    const float* g1 = in + (size_t)(ok1 ? gh1 : 0) * Wd + c;
    const float* g2 = in + (size_t)(ok2 ? gh2 : 0) * Wd + c;

    const uint32_t sbase = (uint32_t)__cvta_generic_to_shared(vsm);
    const uint32_t dst1  = sbase + (uint32_t)(ty * Wd + c) * 4u;
    const uint32_t dst2  = sbase + (uint32_t)(k2 * Wd + c) * 4u;
    const uint32_t BUFB  = BUFSZ * 4u;

    // issue async copies for plane index pf (dl = d0-2+pf) into buf pf%NBUF.
    // pf >= NP: commit an EMPTY group (keeps wait counts aligned, no writes).
    auto issue = [&](int pf) {
        if (pf < NP) {
            int  dl  = d0 - 2 + pf;
            bool dok = ((unsigned)dl < (unsigned)Dd);
            int  dlc = dok ? dl : 0;
            uint32_t boff = (uint32_t)(pf % NBUF) * BUFB;
            cp_async16(dst1 + boff, g1 + (size_t)dlc * PSZ, (ok1 && dok) ? 16 : 0);
            cp_async16(dst2 + boff, g2 + (size_t)dlc * PSZ, (ok2 && dok) ? 16 : 0);
        }
        cp_commit();
    };

    issue(0);
    issue(1);

    // rings (raw domain)
    float4 rp1 = make_float4(0.f, 0.f, 0.f, 0.f);
    float4 rp2 = rp1, rp3 = rp1, rp4 = rp1;          // m2d(p-1..p-4)
    float4 cen1 = rp1, cen2 = rp1;                   // cen(p-1), cen(p-2)

    float* outp = out + (size_t)d0 * PSZ + (size_t)(h0 + ty) * Wd + c;

    // compute one plane from buffer vb; ring update + optional emit
    auto plane = [&](const float* vb, bool emit) {
        const float* vr = vb + ty * Wd + c;
        float4 t0 = *(const float4*)(vr);
        float4 t1 = *(const float4*)(vr + 512);
        float4 t2 = *(const float4*)(vr + 1024);   // center row
        float4 t3 = *(const float4*)(vr + 1536);
        float4 t4 = *(const float4*)(vr + 2048);
        float4 cen = t2;
        float4 hm  = fmax4(fmax4(fmax4(t0, t1), fmax4(t2, t3)), t4);

        float2 eh = make_float2(0.f, 0.f);
        if (haveEdge) {
            const float* ep = vb + ty * Wd + ec;
            float2 e0 = *(const float2*)(ep);
            float2 e1 = *(const float2*)(ep + 512);
            float2 e2 = *(const float2*)(ep + 1024);
            float2 e3 = *(const float2*)(ep + 1536);
            float2 e4 = *(const float2*)(ep + 2048);
            eh.x = fmaxf(fmaxf(fmaxf(e0.x, e1.x), fmaxf(e2.x, e3.x)), e4.x);
            eh.y = fmaxf(fmaxf(fmaxf(e0.y, e1.y), fmaxf(e2.y, e3.y)), e4.y);
        }

        float l2 = __shfl_up_sync(0xffffffffu, hm.z, 1);
        float l1 = __shfl_up_sync(0xffffffffu, hm.w, 1);
        float r4 = __shfl_down_sync(0xffffffffu, hm.x, 1);
        float r5 = __shfl_down_sync(0xffffffffu, hm.y, 1);
        if (edgeL) { l2 = eh.x; l1 = eh.y; }
        if (edgeR) { r4 = eh.x; r5 = eh.y; }

        float m01 = fmaxf(hm.x, hm.y);
        float m12 = fmaxf(hm.y, hm.z);
        float m23 = fmaxf(hm.z, hm.w);
        float4 m;                               // m2d(p), raw
        m.x = fmaxf(fmaxf(l2, l1), fmaxf(m01, hm.z));
        m.y = fmaxf(l1, fmaxf(m01, m23));
        m.z = fmaxf(fmaxf(m01, m23), r4);
        m.w = fmaxf(fmaxf(m12, hm.w), fmaxf(r4, r5));

        if (emit) {
            float4 M3 = fmax4(fmax4(fmax4(rp4, rp3), fmax4(rp2, rp1)), m);
            float4 o;
            o.x = (cen2.x == M3.x && cen2.x > THRESH) ? cen2.x : 0.f;
            o.y = (cen2.y == M3.y && cen2.y > THRESH) ? cen2.y : 0.f;
            o.z = (cen2.z == M3.z && cen2.z > THRESH) ? cen2.z : 0.f;
            o.w = (cen2.w == M3.w && cen2.w > THRESH) ? cen2.w : 0.f;
            *(float4*)outp = o;
            outp += PSZ;
        }

        rp4 = rp3; rp3 = rp2; rp2 = rp1; rp1 = m;
        cen2 = cen1; cen1 = cen;
    };

    #pragma unroll 3
    for (int k = 0; k < NP / 2; ++k) {
        const int p = 2 * k;
        issue(p + 2);
        issue(p + 3);
        cp_wait2();         // planes p, p+1 complete (this thread)
        __syncthreads();    // all threads' copies of planes p, p+1 visible

        plane(vsm + (p % NBUF) * BUFSZ,       p     >= 4);
        plane(vsm + ((p + 1) % NBUF) * BUFSZ, p + 1 >= 4);
    }

    cp_wait0();   // drain trailing groups before exit
}

extern "C" void kernel_launch(void* const* d_in, const int* in_sizes, int n_in,
                              void* d_out, int out_size) {
    (void)in_sizes; (void)n_in; (void)out_size;
    const float* in = (const float*)d_in[0];
    float* out = (float*)d_out;

    const int smem_bytes = NBUF * BUFSZ * (int)sizeof(float);   // 98304
    cudaFuncSetAttribute(peak3d_kernel,
                         cudaFuncAttributeMaxDynamicSharedMemorySize, smem_bytes);

    dim3 block(128, 4);                 // 512 threads
    dim3 grid(Hd / TH, Dd / DCH);       // 128 x 2 = 256 blocks (2/SM resident)
    peak3d_kernel<<<grid, block, smem_bytes>>>(in, out);
}